// round 11
// baseline (speedup 1.0000x reference)
#include <cuda_runtime.h>
#include <cuda_bf16.h>
#include <cstdint>

#define NROWS 10000
#define NFEAT 3000
#define NHID  32
#define KCLUS 10

#define NSPLIT1 3
#define NSPLIT2 7

#define BSTR 72                       // bf16 elems per B smem row (144 B stride)
#define BUFBYTES (32 * BSTR * 2)      // one B buffer: 4608 B

// Partial-sum scratch (plain STG, no zeroing needed: every slot overwritten)
__device__ __align__(16) float g_sup_part[NSPLIT1][NROWS * NHID];
__device__ __align__(16) float g_z_part[NSPLIT2][NROWS * NHID];

__device__ __forceinline__ uint32_t s2u(const void* p) {
    uint32_t a;
    asm("{ .reg .u64 t; cvta.to.shared.u64 t, %1; cvt.u32.u64 %0, t; }" : "=r"(a) : "l"(p));
    return a;
}

// fp32 pair -> packed bf16 hi pair + bf16 residual pair
__device__ __forceinline__ void split2(float x, float y, uint32_t& h, uint32_t& l) {
    __nv_bfloat162 hb = __floats2bfloat162_rn(x, y);
    float2 hf = __bfloat1622float2(hb);
    __nv_bfloat162 lb = __floats2bfloat162_rn(x - hf.x, y - hf.y);
    h = *reinterpret_cast<uint32_t*>(&hb);
    l = *reinterpret_cast<uint32_t*>(&lb);
}

#define MMA_BF16(dd, a, b0, b1)                                              \
    asm volatile(                                                            \
        "mma.sync.aligned.m16n8k16.row.col.f32.bf16.bf16.f32 "               \
        "{%0,%1,%2,%3}, {%4,%5,%6,%7}, {%8,%9}, {%0,%1,%2,%3};"              \
        : "+f"(dd[0]), "+f"(dd[1]), "+f"(dd[2]), "+f"(dd[3])                 \
        : "r"(a[0]), "r"(a[1]), "r"(a[2]), "r"(a[3]), "r"(b0), "r"(b1))

#define LDSM4(r0, r1, r2, r3, addr)                                          \
    asm volatile(                                                            \
        "ldmatrix.sync.aligned.m8n8.x4.shared.b16 {%0,%1,%2,%3}, [%4];"      \
        : "=r"(r0), "=r"(r1), "=r"(r2), "=r"(r3) : "r"(addr))

// ---------------------------------------------------------------------------
// Cpart[M,32] = A[M,K_slice] @ Bsum[K,32] for this CTA's K-slice.
// Bsum = sum of NP partial input buffers (NP=1: plain input; NP=3: gemm1 parts).
// A frags direct from global; B via double-buffered smem + ldmatrix.x4.
// Output: plain STG into per-split partial buffer (no atomics).
// ---------------------------------------------------------------------------
template <int NP>
__global__ __launch_bounds__(256, 2)
void gemm_mma(const float* __restrict__ A, const float* __restrict__ B,
              float* __restrict__ Cbase, int M, int K, int klen) {
    __shared__ __nv_bfloat16 Bh[2][32 * BSTR];
    __shared__ __nv_bfloat16 Bl[2][32 * BSTR];

    const int tid  = threadIdx.x;
    const int warp = tid >> 5, lane = tid & 31;
    const int g    = lane >> 2, tg = lane & 3;
    const int wm   = warp * 16;
    const int row0 = blockIdx.x * 128;
    const int kbeg = blockIdx.y * klen;          // klen mult of 64
    const int kend = min(kbeg + klen, K);
    const int nch  = (kend > kbeg) ? ((kend - kbeg + 63) >> 6) : 0;
    const size_t pstride = (size_t)M * NHID;     // partial-buffer stride

    const int gr0 = row0 + wm + g;
    const bool r0ok = gr0 < M, r8ok = gr0 + 8 < M;
    const float* __restrict__ Ar0 = A + (size_t)gr0 * K;
    const float* __restrict__ Ar8 = Ar0 + (size_t)8 * K;

    const int lt = lane >> 3, lr = lane & 7;
    const uint32_t bh0a = s2u(&Bh[0][0]);
    const uint32_t bl0a = s2u(&Bl[0][0]);
    uint32_t rowoff[2];
#pragma unroll
    for (int p = 0; p < 2; p++)
        rowoff[p] = (uint32_t)(((p * 16 + (lt >> 1) * 8 + lr) * BSTR) * 2 + (lt & 1) * 16);

    float d[4][4];
#pragma unroll
    for (int i = 0; i < 4; i++)
#pragma unroll
        for (int j = 0; j < 4; j++) d[i][j] = 0.f;

    float2   va[16];
    float    vb[8];
    uint32_t ah[4][4], al[4][4];
    const float2 f2z = make_float2(0.f, 0.f);

#define LOADA(k0)                                                              \
    {                                                                          \
        _Pragma("unroll")                                                      \
        for (int ks = 0; ks < 4; ks++) {                                       \
            int gk0 = (k0) + ks * 16 + tg * 2;                                 \
            int gk1 = gk0 + 8;                                                 \
            va[ks*4+0] = (r0ok && gk0 < kend) ? *(const float2*)(Ar0+gk0) : f2z; \
            va[ks*4+1] = (r8ok && gk0 < kend) ? *(const float2*)(Ar8+gk0) : f2z; \
            va[ks*4+2] = (r0ok && gk1 < kend) ? *(const float2*)(Ar0+gk1) : f2z; \
            va[ks*4+3] = (r8ok && gk1 < kend) ? *(const float2*)(Ar8+gk1) : f2z; \
        }                                                                      \
    }

#define LOADB(k0)                                                              \
    {                                                                          \
        _Pragma("unroll")                                                      \
        for (int i = 0; i < 2; i++) {                                          \
            int f = tid + i * 256;                                             \
            int n = f & 31, kq = f >> 5;                                       \
            _Pragma("unroll")                                                  \
            for (int j = 0; j < 4; j++) {                                      \
                int kk = (k0) + kq * 4 + j;                                    \
                float s = 0.f;                                                 \
                if (kk < kend) {                                               \
                    _Pragma("unroll")                                          \
                    for (int p = 0; p < NP; p++)                               \
                        s += B[p * pstride + (size_t)kk * NHID + n];           \
                }                                                              \
                vb[i*4+j] = s;                                                 \
            }                                                                  \
        }                                                                      \
    }

#define CONVA                                                                  \
    {                                                                          \
        _Pragma("unroll")                                                      \
        for (int ks = 0; ks < 4; ks++)                                         \
            _Pragma("unroll")                                                  \
            for (int j = 0; j < 4; j++)                                        \
                split2(va[ks*4+j].x, va[ks*4+j].y, ah[ks][j], al[ks][j]);      \
    }

#define STSB(bf)                                                               \
    {                                                                          \
        _Pragma("unroll")                                                      \
        for (int i = 0; i < 2; i++) {                                          \
            int f = tid + i * 256;                                             \
            int n = f & 31, kq = f >> 5;                                       \
            uint32_t h0, l0, h1, l1;                                           \
            split2(vb[i*4+0], vb[i*4+1], h0, l0);                              \
            split2(vb[i*4+2], vb[i*4+3], h1, l1);                              \
            int e = n * BSTR + kq * 4;                                         \
            *(uint2*)&Bh[bf][e] = make_uint2(h0, h1);                          \
            *(uint2*)&Bl[bf][e] = make_uint2(l0, l1);                          \
        }                                                                      \
    }

    if (nch > 0) {
        LOADA(kbeg); LOADB(kbeg);
        STSB(0); CONVA;
        __syncthreads();
    }

    for (int c = 0; c < nch; c++) {
        const int  buf  = c & 1;
        const bool more = (c + 1 < nch);
        const int  nk   = kbeg + (c + 1) * 64;
        const uint32_t bha = bh0a + buf * BUFBYTES;
        const uint32_t bla = bl0a + buf * BUFBYTES;

        if (more) { LOADA(nk); LOADB(nk); }   // LDG latency hides behind MMAs

        // ---- compute chunk c ----
#pragma unroll
        for (int ks = 0; ks < 4; ks++) {
            uint32_t bh[2][4], bl[2][4];
#pragma unroll
            for (int p = 0; p < 2; p++) {
                uint32_t ko = (uint32_t)(ks * 32);
                LDSM4(bh[p][0], bh[p][1], bh[p][2], bh[p][3], bha + rowoff[p] + ko);
                LDSM4(bl[p][0], bl[p][1], bl[p][2], bl[p][3], bla + rowoff[p] + ko);
            }
#pragma unroll
            for (int j = 0; j < 4; j++)
                MMA_BF16(d[j], ah[ks], bh[j >> 1][(j & 1) * 2], bh[j >> 1][(j & 1) * 2 + 1]);
#pragma unroll
            for (int j = 0; j < 4; j++)
                MMA_BF16(d[j], ah[ks], bl[j >> 1][(j & 1) * 2], bl[j >> 1][(j & 1) * 2 + 1]);
#pragma unroll
            for (int j = 0; j < 4; j++)
                MMA_BF16(d[j], al[ks], bh[j >> 1][(j & 1) * 2], bh[j >> 1][(j & 1) * 2 + 1]);
        }

        if (more) { STSB(buf ^ 1); CONVA; }
        __syncthreads();
    }

    // ---- epilogue: plain STG into this split's partial buffer ----
    float* __restrict__ Cp = Cbase + (size_t)blockIdx.y * pstride;
#pragma unroll
    for (int nt = 0; nt < 4; nt++) {
        int c0 = nt * 8 + tg * 2;
        if (r0ok)
            *(float2*)&Cp[(size_t)gr0 * NHID + c0] = make_float2(d[nt][0], d[nt][1]);
        if (r8ok)
            *(float2*)&Cp[(size_t)(gr0 + 8) * NHID + c0] = make_float2(d[nt][2], d[nt][3]);
    }
#undef LOADA
#undef LOADB
#undef CONVA
#undef STSB
}

// ---------------------------------------------------------------------------
// Finalize: z = sum_7 z_part + b (write), student-t q (write).
// 8 lanes per row (4 h-values each), 4 rows per warp.
// ---------------------------------------------------------------------------
__global__ __launch_bounds__(256)
void finalize_kernel(const float* __restrict__ b, const float* __restrict__ mu,
                     float* __restrict__ out) {
    const int lane = threadIdx.x & 31;
    const int warp = (blockIdx.x * blockDim.x + threadIdx.x) >> 5;
    const int row  = warp * 4 + (lane >> 3);
    const int sub  = lane & 7;          // 8 lanes per row
    const int hb   = sub * 4;           // this lane's 4 hidden dims
    if (row >= NROWS) return;

    // z (4 components) = sum of partials + bias
    float4 zv = *(const float4*)&g_z_part[0][(size_t)row * NHID + hb];
#pragma unroll
    for (int p = 1; p < NSPLIT2; p++) {
        float4 t = *(const float4*)&g_z_part[p][(size_t)row * NHID + hb];
        zv.x += t.x; zv.y += t.y; zv.z += t.z; zv.w += t.w;
    }
    {
        float4 bv = *(const float4*)&b[hb];
        zv.x += bv.x; zv.y += bv.y; zv.z += bv.z; zv.w += bv.w;
    }
    *(float4*)&out[(size_t)row * NHID + hb] = zv;

    // distances: 3-level xor all-reduce within the 8-lane group
    float d2[KCLUS];
#pragma unroll
    for (int j = 0; j < KCLUS; j++) {
        float4 m = *(const float4*)&mu[j * NHID + hb];
        float dx = zv.x - m.x, dy = zv.y - m.y, dz = zv.z - m.z, dw = zv.w - m.w;
        float v = dx * dx + dy * dy + dz * dz + dw * dw;
        v += __shfl_xor_sync(0xffffffffu, v, 1);
        v += __shfl_xor_sync(0xffffffffu, v, 2);
        v += __shfl_xor_sync(0xffffffffu, v, 4);
        d2[j] = v;
    }

    float qv[KCLUS], ssum = 0.f;
#pragma unroll
    for (int j = 0; j < KCLUS; j++) {
        float base = 1.0f / (1.0f + d2[j] * 5.0f + 1e-8f);  // ALPHA = 0.2
        qv[j] = 0.5f * __powf(base, 1.2f);                  // ^(ALPHA+1) / 2
        ssum += qv[j];
    }
    float inv = 1.0f / ssum;
    float* qrow = out + (size_t)NROWS * NHID + (size_t)row * KCLUS;
    qrow[sub] = qv[sub] * inv;          // q[0..7]
    if (sub < 2) qrow[8 + sub] = qv[8 + sub] * inv;  // q[8..9]
}

// ---------------------------------------------------------------------------
extern "C" void kernel_launch(void* const* d_in, const int* in_sizes, int n_in,
                              void* d_out, int out_size) {
    const float* x   = (const float*)d_in[0];  // [10000, 3000]
    const float* adj = (const float*)d_in[1];  // [10000, 10000]
    const float* W   = (const float*)d_in[2];  // [3000, 32]
    const float* b   = (const float*)d_in[3];  // [32]
    const float* mu  = (const float*)d_in[4];  // [10, 32]
    float* out = (float*)d_out;                // z [10000,32] then q [10000,10]

    float *sup, *zbuf;
    cudaGetSymbolAddress((void**)&sup,  g_sup_part);
    cudaGetSymbolAddress((void**)&zbuf, g_z_part);

    // support partials = x @ W : 79 tiles x 3 splits (klen mult of 64)
    {
        dim3 grid(79, NSPLIT1);
        gemm_mma<1><<<grid, 256>>>(x, W, sup, NROWS, NFEAT, 1024);
    }
    // z partials = adj @ (sum of 3 support partials) : 79 tiles x 7 splits
    {
        dim3 grid(79, NSPLIT2);
        gemm_mma<NSPLIT1><<<grid, 256>>>(adj, sup, zbuf, NROWS, NROWS, 1472);
    }
    // bias + partial reduction + soft assignment
    {
        int rows_per_block = 32;                    // 8 warps x 4 rows
        int blocks = (NROWS + rows_per_block - 1) / rows_per_block;
        finalize_kernel<<<blocks, 256>>>(b, mu, out);
    }
}

// round 12
// speedup vs baseline: 1.1920x; 1.1920x over previous
#include <cuda_runtime.h>
#include <cuda_bf16.h>
#include <cstdint>

#define NROWS 10000
#define NFEAT 3000
#define NHID  32
#define KCLUS 10

#define NSPLIT1 5
#define NSPLIT2 5

#define BSTR 40                       // bf16 elems per B smem row (80 B stride)
#define BUFBYTES (32 * BSTR * 2)      // one B buffer: 2560 B

// Partial-sum scratch (plain STG, no zeroing: every slot overwritten each run)
__device__ __align__(16) float g_sup_part[NSPLIT1][NROWS * NHID];
__device__ __align__(16) float g_support[NROWS * NHID];
__device__ __align__(16) float g_z_part[NSPLIT2][NROWS * NHID];

__device__ __forceinline__ uint32_t s2u(const void* p) {
    uint32_t a;
    asm("{ .reg .u64 t; cvta.to.shared.u64 t, %1; cvt.u32.u64 %0, t; }" : "=r"(a) : "l"(p));
    return a;
}

// fp32 pair -> packed bf16 hi pair + bf16 residual pair
__device__ __forceinline__ void split2(float x, float y, uint32_t& h, uint32_t& l) {
    __nv_bfloat162 hb = __floats2bfloat162_rn(x, y);
    float2 hf = __bfloat1622float2(hb);
    __nv_bfloat162 lb = __floats2bfloat162_rn(x - hf.x, y - hf.y);
    h = *reinterpret_cast<uint32_t*>(&hb);
    l = *reinterpret_cast<uint32_t*>(&lb);
}

#define MMA_BF16(dd, a, b0, b1)                                              \
    asm volatile(                                                            \
        "mma.sync.aligned.m16n8k16.row.col.f32.bf16.bf16.f32 "               \
        "{%0,%1,%2,%3}, {%4,%5,%6,%7}, {%8,%9}, {%0,%1,%2,%3};"              \
        : "+f"(dd[0]), "+f"(dd[1]), "+f"(dd[2]), "+f"(dd[3])                 \
        : "r"(a[0]), "r"(a[1]), "r"(a[2]), "r"(a[3]), "r"(b0), "r"(b1))

#define LDSM4(r0, r1, r2, r3, addr)                                          \
    asm volatile(                                                            \
        "ldmatrix.sync.aligned.m8n8.x4.shared.b16 {%0,%1,%2,%3}, [%4];"      \
        : "=r"(r0), "=r"(r1), "=r"(r2), "=r"(r3) : "r"(addr))

// ---------------------------------------------------------------------------
// g_support = sum of NSPLIT1 gemm1 partials (L2-resident, trivially fast)
// ---------------------------------------------------------------------------
__global__ __launch_bounds__(256)
void reduce_sup() {
    int i = blockIdx.x * blockDim.x + threadIdx.x;
    if (i < (NROWS * NHID) / 4) {
        float4 s = ((const float4*)g_sup_part[0])[i];
#pragma unroll
        for (int p = 1; p < NSPLIT1; p++) {
            float4 t = ((const float4*)g_sup_part[p])[i];
            s.x += t.x; s.y += t.y; s.z += t.z; s.w += t.w;
        }
        ((float4*)g_support)[i] = s;
    }
}

// ---------------------------------------------------------------------------
// Cpart[M,32] = A[M,K_slice] @ B[K,32] for this CTA's K-slice.
// BK=32, 3 CTAs/SM (occupancy-driven), A frags direct from global,
// B via double-buffered smem + ldmatrix.x4, plain-STG partial output.
// ---------------------------------------------------------------------------
__global__ __launch_bounds__(256, 3)
void gemm_mma(const float* __restrict__ A, const float* __restrict__ B,
              float* __restrict__ Cbase, int M, int K, int klen) {
    __shared__ __nv_bfloat16 Bh[2][32 * BSTR];
    __shared__ __nv_bfloat16 Bl[2][32 * BSTR];

    const int tid  = threadIdx.x;
    const int warp = tid >> 5, lane = tid & 31;
    const int g    = lane >> 2, tg = lane & 3;
    const int row0 = blockIdx.x * 128;
    const int kbeg = blockIdx.y * klen;          // klen mult of 32 -> even
    const int kend = min(kbeg + klen, K);
    const int nch  = (kend > kbeg) ? ((kend - kbeg + 31) >> 5) : 0;
    const size_t pstride = (size_t)M * NHID;

    const int gr0 = row0 + warp * 16 + g;
    const bool r0ok = gr0 < M, r8ok = gr0 + 8 < M;
    const float* __restrict__ Ar0 = A + (size_t)gr0 * K;
    const float* __restrict__ Ar8 = Ar0 + (size_t)8 * K;

    const int lt = lane >> 3, lr = lane & 7;
    const uint32_t bh0a = s2u(&Bh[0][0]);
    const uint32_t bl0a = s2u(&Bl[0][0]);
    uint32_t rowoff[2];
#pragma unroll
    for (int p = 0; p < 2; p++)
        rowoff[p] = (uint32_t)(((p * 16 + (lt >> 1) * 8 + lr) * BSTR) * 2 + (lt & 1) * 16);

    float d[4][4];
#pragma unroll
    for (int i = 0; i < 4; i++)
#pragma unroll
        for (int j = 0; j < 4; j++) d[i][j] = 0.f;

    float2   va[8];                 // raw A frags, one BK=32 chunk
    float    vb[4];                 // raw B slice
    uint32_t ah[2][4], al[2][4];
    const float2 f2z = make_float2(0.f, 0.f);

#define LOADA(k0)                                                              \
    {                                                                          \
        _Pragma("unroll")                                                      \
        for (int ks = 0; ks < 2; ks++) {                                       \
            int gk0 = (k0) + ks * 16 + tg * 2;                                 \
            int gk1 = gk0 + 8;                                                 \
            va[ks*4+0] = (r0ok && gk0 < kend) ? *(const float2*)(Ar0+gk0) : f2z; \
            va[ks*4+1] = (r8ok && gk0 < kend) ? *(const float2*)(Ar8+gk0) : f2z; \
            va[ks*4+2] = (r0ok && gk1 < kend) ? *(const float2*)(Ar0+gk1) : f2z; \
            va[ks*4+3] = (r8ok && gk1 < kend) ? *(const float2*)(Ar8+gk1) : f2z; \
        }                                                                      \
    }

#define LOADB(k0)                                                              \
    {                                                                          \
        int n = tid & 31, kq = tid >> 5;   /* kq in [0,8): k 0..31 */          \
        _Pragma("unroll")                                                      \
        for (int j = 0; j < 4; j++) {                                          \
            int kk = (k0) + kq * 4 + j;                                        \
            vb[j] = (kk < kend) ? B[(size_t)kk * NHID + n] : 0.f;              \
        }                                                                      \
    }

#define CONVA                                                                  \
    {                                                                          \
        _Pragma("unroll")                                                      \
        for (int ks = 0; ks < 2; ks++)                                         \
            _Pragma("unroll")                                                  \
            for (int j = 0; j < 4; j++)                                        \
                split2(va[ks*4+j].x, va[ks*4+j].y, ah[ks][j], al[ks][j]);      \
    }

#define STSB(bf)                                                               \
    {                                                                          \
        int n = tid & 31, kq = tid >> 5;                                       \
        uint32_t h0, l0, h1, l1;                                               \
        split2(vb[0], vb[1], h0, l0);                                          \
        split2(vb[2], vb[3], h1, l1);                                          \
        int e = n * BSTR + kq * 4;                                             \
        *(uint2*)&Bh[bf][e] = make_uint2(h0, h1);                              \
        *(uint2*)&Bl[bf][e] = make_uint2(l0, l1);                              \
    }

    if (nch > 0) {
        LOADA(kbeg); LOADB(kbeg);
        STSB(0); CONVA;
        __syncthreads();
    }

    for (int c = 0; c < nch; c++) {
        const int  buf  = c & 1;
        const bool more = (c + 1 < nch);
        const int  nk   = kbeg + (c + 1) * 32;
        const uint32_t bha = bh0a + buf * BUFBYTES;
        const uint32_t bla = bl0a + buf * BUFBYTES;

        if (more) { LOADA(nk); LOADB(nk); }   // LDG latency hides behind MMAs

        // ---- compute chunk c: 2 k16-steps x (8 LDSM4 + 24 MMA) ----
#pragma unroll
        for (int ks = 0; ks < 2; ks++) {
            uint32_t bh[2][4], bl[2][4];
#pragma unroll
            for (int p = 0; p < 2; p++) {
                uint32_t ko = (uint32_t)(ks * 32);
                LDSM4(bh[p][0], bh[p][1], bh[p][2], bh[p][3], bha + rowoff[p] + ko);
                LDSM4(bl[p][0], bl[p][1], bl[p][2], bl[p][3], bla + rowoff[p] + ko);
            }
#pragma unroll
            for (int j = 0; j < 4; j++)
                MMA_BF16(d[j], ah[ks], bh[j >> 1][(j & 1) * 2], bh[j >> 1][(j & 1) * 2 + 1]);
#pragma unroll
            for (int j = 0; j < 4; j++)
                MMA_BF16(d[j], ah[ks], bl[j >> 1][(j & 1) * 2], bl[j >> 1][(j & 1) * 2 + 1]);
#pragma unroll
            for (int j = 0; j < 4; j++)
                MMA_BF16(d[j], al[ks], bh[j >> 1][(j & 1) * 2], bh[j >> 1][(j & 1) * 2 + 1]);
        }

        if (more) { STSB(buf ^ 1); CONVA; }
        __syncthreads();
    }

    // ---- epilogue: plain STG into this split's partial buffer ----
    float* __restrict__ Cp = Cbase + (size_t)blockIdx.y * pstride;
#pragma unroll
    for (int nt = 0; nt < 4; nt++) {
        int c0 = nt * 8 + tg * 2;
        if (r0ok)
            *(float2*)&Cp[(size_t)gr0 * NHID + c0] = make_float2(d[nt][0], d[nt][1]);
        if (r8ok)
            *(float2*)&Cp[(size_t)(gr0 + 8) * NHID + c0] = make_float2(d[nt][2], d[nt][3]);
    }
#undef LOADA
#undef LOADB
#undef CONVA
#undef STSB
}

// ---------------------------------------------------------------------------
// Finalize: z = sum of z partials + b (write), student-t q (write).
// 8 lanes per row (4 h-values each), 4 rows per warp.
// ---------------------------------------------------------------------------
__global__ __launch_bounds__(256)
void finalize_kernel(const float* __restrict__ b, const float* __restrict__ mu,
                     float* __restrict__ out) {
    const int lane = threadIdx.x & 31;
    const int warp = (blockIdx.x * blockDim.x + threadIdx.x) >> 5;
    const int row  = warp * 4 + (lane >> 3);
    const int sub  = lane & 7;
    const int hb   = sub * 4;
    if (row >= NROWS) return;

    float4 zv = *(const float4*)&g_z_part[0][(size_t)row * NHID + hb];
#pragma unroll
    for (int p = 1; p < NSPLIT2; p++) {
        float4 t = *(const float4*)&g_z_part[p][(size_t)row * NHID + hb];
        zv.x += t.x; zv.y += t.y; zv.z += t.z; zv.w += t.w;
    }
    {
        float4 bv = *(const float4*)&b[hb];
        zv.x += bv.x; zv.y += bv.y; zv.z += bv.z; zv.w += bv.w;
    }
    *(float4*)&out[(size_t)row * NHID + hb] = zv;

    float d2[KCLUS];
#pragma unroll
    for (int j = 0; j < KCLUS; j++) {
        float4 m = *(const float4*)&mu[j * NHID + hb];
        float dx = zv.x - m.x, dy = zv.y - m.y, dz = zv.z - m.z, dw = zv.w - m.w;
        float v = dx * dx + dy * dy + dz * dz + dw * dw;
        v += __shfl_xor_sync(0xffffffffu, v, 1);
        v += __shfl_xor_sync(0xffffffffu, v, 2);
        v += __shfl_xor_sync(0xffffffffu, v, 4);
        d2[j] = v;
    }

    float qv[KCLUS], ssum = 0.f;
#pragma unroll
    for (int j = 0; j < KCLUS; j++) {
        float base = 1.0f / (1.0f + d2[j] * 5.0f + 1e-8f);  // ALPHA = 0.2
        qv[j] = 0.5f * __powf(base, 1.2f);                  // ^(ALPHA+1) / 2
        ssum += qv[j];
    }
    float inv = 1.0f / ssum;
    float* qrow = out + (size_t)NROWS * NHID + (size_t)row * KCLUS;
    qrow[sub] = qv[sub] * inv;
    if (sub < 2) qrow[8 + sub] = qv[8 + sub] * inv;
}

// ---------------------------------------------------------------------------
extern "C" void kernel_launch(void* const* d_in, const int* in_sizes, int n_in,
                              void* d_out, int out_size) {
    const float* x   = (const float*)d_in[0];  // [10000, 3000]
    const float* adj = (const float*)d_in[1];  // [10000, 10000]
    const float* W   = (const float*)d_in[2];  // [3000, 32]
    const float* b   = (const float*)d_in[3];  // [32]
    const float* mu  = (const float*)d_in[4];  // [10, 32]
    float* out = (float*)d_out;                // z [10000,32] then q [10000,10]

    float *supp, *sup, *zbuf;
    cudaGetSymbolAddress((void**)&supp, g_sup_part);
    cudaGetSymbolAddress((void**)&sup,  g_support);
    cudaGetSymbolAddress((void**)&zbuf, g_z_part);

    // support partials = x @ W : 79 tiles x 5 splits (klen 608, mult of 32)
    {
        dim3 grid(79, NSPLIT1);
        gemm_mma<<<grid, 256>>>(x, W, supp, NROWS, NFEAT, 608);
    }
    // g_support = sum of 5 partials (L2-resident)
    reduce_sup<<<(NROWS * NHID / 4 + 255) / 256, 256>>>();

    // z partials = adj @ g_support : 79 tiles x 5 splits (klen 2016)
    {
        dim3 grid(79, NSPLIT2);
        gemm_mma<<<grid, 256>>>(adj, sup, zbuf, NROWS, NROWS, 2016);
    }
    // bias + partial reduction + soft assignment
    {
        int blocks = (NROWS + 31) / 32;   // 8 warps x 4 rows per block
        finalize_kernel<<<blocks, 256>>>(b, mu, out);
    }
}